// round 5
// baseline (speedup 1.0000x reference)
#include <cuda_runtime.h>
#include <cuda_bf16.h>
#include <cstdint>

#define DCH   512
#define HW    4096
#define NROWS 65536
#define KCB   1024
#define LOSS_OFF 33554432
#define PROB_OFF 33554433

// ---------------- device scratch ----------------
__device__ float g_cnorm[KCB];
__device__ float g_znorm[NROWS];
__device__ int   g_minidx[NROWS];
__device__ float g_partial[8192];
__device__ __nv_bfloat16 g_zhi[(size_t)NROWS * DCH];
__device__ __nv_bfloat16 g_zlo[(size_t)NROWS * DCH];
__device__ __nv_bfloat16 g_chi[(size_t)KCB * DCH];
__device__ __nv_bfloat16 g_clo[(size_t)KCB * DCH];
__device__ float g_dist[(size_t)NROWS * KCB];

// ---------------- PTX helpers (sm_80-era, plain-target legal) ----------------
__device__ __forceinline__ uint32_t smem_u32(const void* p) {
    uint32_t a;
    asm("{ .reg .u64 t; cvta.to.shared.u64 t, %1; cvt.u32.u64 %0, t; }" : "=r"(a) : "l"(p));
    return a;
}
__device__ __forceinline__ void cpasync16(uint32_t s, const void* g) {
    asm volatile("cp.async.cg.shared.global [%0], [%1], 16;" :: "r"(s), "l"(g));
}
__device__ __forceinline__ void cpasync4(uint32_t s, const void* g) {
    asm volatile("cp.async.ca.shared.global [%0], [%1], 4;" :: "r"(s), "l"(g));
}
#define CP_COMMIT()  asm volatile("cp.async.commit_group;" ::: "memory")
#define CP_WAIT1()   asm volatile("cp.async.wait_group 1;" ::: "memory")
#define CP_WAIT0()   asm volatile("cp.async.wait_group 0;" ::: "memory")
#define BAR(id, cnt) asm volatile("bar.sync %0, %1;" :: "r"(id), "r"(cnt) : "memory")

#define LDSM_X4(r0, r1, r2, r3, addr)                                          \
    asm volatile("ldmatrix.sync.aligned.m8n8.x4.shared.b16 {%0,%1,%2,%3}, [%4];" \
                 : "=r"(r0), "=r"(r1), "=r"(r2), "=r"(r3) : "r"(addr))

#define MMA16816(d, a, b0, b1)                                                 \
    asm volatile("mma.sync.aligned.m16n8k16.row.col.f32.bf16.bf16.f32 "        \
                 "{%0,%1,%2,%3}, {%4,%5,%6,%7}, {%8,%9}, {%0,%1,%2,%3};"       \
                 : "+f"((d)[0]), "+f"((d)[1]), "+f"((d)[2]), "+f"((d)[3])      \
                 : "r"((a)[0]), "r"((a)[1]), "r"((a)[2]), "r"((a)[3]),         \
                   "r"(b0), "r"(b1))

// ---------------------------------------------------------------------------
// cnorm: sequential fp32 (replicates reference rounding)
// ---------------------------------------------------------------------------
__global__ void k_cnorm(const float* __restrict__ cb) {
    int j = blockIdx.x * blockDim.x + threadIdx.x;
    if (j >= KCB) return;
    const float* r = cb + (size_t)j * DCH;
    float acc = 0.f;
    for (int k = 0; k < DCH; ++k) {
        float v = r[k];
        acc = __fadd_rn(acc, __fmul_rn(v, v));
    }
    g_cnorm[j] = acc;
}

// ---------------------------------------------------------------------------
// codebook bf16 hi/lo split
// ---------------------------------------------------------------------------
__global__ void k_csplit(const float* __restrict__ cb) {
    int idx = blockIdx.x * blockDim.x + threadIdx.x;
    if (idx >= (KCB * DCH) / 2) return;
    float2 v = ((const float2*)cb)[idx];
    __nv_bfloat162 h = __floats2bfloat162_rn(v.x, v.y);
    float2 hf = make_float2(__bfloat162float(__low2bfloat16(h)),
                            __bfloat162float(__high2bfloat16(h)));
    __nv_bfloat162 l = __floats2bfloat162_rn(v.x - hf.x, v.y - hf.y);
    ((__nv_bfloat162*)g_chi)[idx] = h;
    ((__nv_bfloat162*)g_clo)[idx] = l;
}

// ---------------------------------------------------------------------------
// z bf16 hi/lo split + FUSED znorm (exact sequential d-order per row)
// ---------------------------------------------------------------------------
__global__ __launch_bounds__(256)
void k_zsplit(const float* __restrict__ z) {
    __shared__ float sm[64 * 65];
    const int tid  = threadIdx.x;
    const int bi   = blockIdx.x >> 6;
    const int rem0 = (blockIdx.x & 63) << 6;
    const float* zb = z + (size_t)bi * (DCH * HW) + rem0;
    float zacc = 0.f;

    for (int kt = 0; kt < 8; ++kt) {
        __syncthreads();
        int k0 = kt * 64;
#pragma unroll
        for (int it = 0; it < 16; ++it) {
            int li = it * 256 + tid;
            int r = li & 63, k = li >> 6;
            sm[k * 65 + r] = zb[(size_t)(k0 + k) * HW + r];
        }
        __syncthreads();
        // znorm: thread t<64 owns row t, adds its 64 d-values in order
        if (tid < 64) {
#pragma unroll 8
            for (int k = 0; k < 64; ++k) {
                float v = sm[k * 65 + tid];
                zacc = __fadd_rn(zacc, __fmul_rn(v, v));
            }
        }
        int r  = tid >> 2;
        int kq = tid & 3;
        uint32_t hbuf[8], lbuf[8];
#pragma unroll
        for (int i = 0; i < 8; ++i) {
            float v0 = sm[(kq * 16 + 2 * i)     * 65 + r];
            float v1 = sm[(kq * 16 + 2 * i + 1) * 65 + r];
            __nv_bfloat162 h = __floats2bfloat162_rn(v0, v1);
            float h0 = __bfloat162float(__low2bfloat16(h));
            float h1 = __bfloat162float(__high2bfloat16(h));
            __nv_bfloat162 l = __floats2bfloat162_rn(v0 - h0, v1 - h1);
            hbuf[i] = *(uint32_t*)&h;
            lbuf[i] = *(uint32_t*)&l;
        }
        size_t base = ((size_t)(bi * 4096 + rem0 + r)) * DCH + k0 + kq * 16;
        *(uint4*)((char*)g_zhi + base * 2)      = *(uint4*)(hbuf);
        *(uint4*)((char*)g_zhi + base * 2 + 16) = *(uint4*)(hbuf + 4);
        *(uint4*)((char*)g_zlo + base * 2)      = *(uint4*)(lbuf);
        *(uint4*)((char*)g_zlo + base * 2 + 16) = *(uint4*)(lbuf + 4);
    }
    if (tid < 64) g_znorm[bi * 4096 + rem0 + tid] = zacc;
}

// ---------------------------------------------------------------------------
// Hybrid GEMM: 8 tensor warps (K 0..383, 3-term bf16 HMMA) + 4 fp32 warps
// (K 384..511, exact fp32 FFMA). Partials joined in smem; dist written.
// ---------------------------------------------------------------------------
#define PITCH 80
#define T_A_HI 0
#define T_A_LO 10240
#define T_B_HI 20480
#define T_B_LO 30720
#define STAGE_BYTES 40960
#define S_CN  81920
#define S_ZN  82432
#define F_Z   82944
#define F_C   91136
#define S_PB  99328
#define GEMM_SMEM 165888
#define KC_T 12            // tensor k-chunks (K = 384)
#define KF0  384           // fp32 K start

__global__ __launch_bounds__(384, 1)
void k_gemm(const float* __restrict__ z, const float* __restrict__ cb) {
    extern __shared__ char smem[];
    const uint32_t sb = smem_u32(smem);
    const int tid   = threadIdx.x;
    const int rowblk = blockIdx.x >> 3;
    const int nblk   = blockIdx.x & 7;
    const int row0   = rowblk << 7;
    const int n0     = nblk << 7;
    const int bi     = row0 >> 12;
    const int rem0   = row0 & 4095;

    float* s_cn = (float*)(smem + S_CN);
    float* s_zn = (float*)(smem + S_ZN);
    float* pbuf = (float*)(smem + S_PB);     // [128][130]

    if (tid < 256) {
        // ================= TENSOR GROUP =================
        const int lane = tid & 31;
        const int wid  = tid >> 5;
        const int wm   = wid & 3;
        const int wn   = wid >> 2;
        const int srow = tid >> 2;
        const int sch  = tid & 3;

        const char* gAh = (const char*)g_zhi + ((size_t)(row0 + srow) << 10) + sch * 16;
        const char* gAl = (const char*)g_zlo + ((size_t)(row0 + srow) << 10) + sch * 16;
        const char* gBh = (const char*)g_chi + ((size_t)(n0   + srow) << 10) + sch * 16;
        const char* gBl = (const char*)g_clo + ((size_t)(n0   + srow) << 10) + sch * 16;
        const uint32_t sOff = srow * PITCH + sch * 16;

#define LOAD_STAGE(stg, kc) do {                                               \
    uint32_t s0 = sb + (stg) * STAGE_BYTES + sOff;                             \
    size_t   go = (size_t)(kc) * 64;                                           \
    cpasync16(s0 + T_A_HI,              gAh + go);                             \
    cpasync16(s0 + T_A_HI + 64 * PITCH, gAh + go + (size_t)64 * 1024);         \
    cpasync16(s0 + T_A_LO,              gAl + go);                             \
    cpasync16(s0 + T_A_LO + 64 * PITCH, gAl + go + (size_t)64 * 1024);         \
    cpasync16(s0 + T_B_HI,              gBh + go);                             \
    cpasync16(s0 + T_B_HI + 64 * PITCH, gBh + go + (size_t)64 * 1024);         \
    cpasync16(s0 + T_B_LO,              gBl + go);                             \
    cpasync16(s0 + T_B_LO + 64 * PITCH, gBl + go + (size_t)64 * 1024);         \
    CP_COMMIT();                                                               \
} while (0)

        LOAD_STAGE(0, 0);

        float acc[2][8][4];
#pragma unroll
        for (int mi = 0; mi < 2; ++mi)
#pragma unroll
            for (int n8 = 0; n8 < 8; ++n8)
#pragma unroll
                for (int e = 0; e < 4; ++e) acc[mi][n8][e] = 0.f;

        const int aRow = (lane & 15);
        const int aChk = (lane >> 4);
        const int bRow = (lane & 7) + ((lane >> 4) << 3);
        const int bChk = ((lane >> 3) & 1);

        for (int kc = 0; kc < KC_T; ++kc) {
            if (kc + 1 < KC_T) LOAD_STAGE((kc + 1) & 1, kc + 1);
            if (kc + 1 < KC_T) { CP_WAIT1(); } else { CP_WAIT0(); }
            BAR(1, 256);

            const uint32_t st = sb + (kc & 1) * STAGE_BYTES;
#pragma unroll
            for (int ks = 0; ks < 2; ++ks) {
                uint32_t ah[2][4], al[2][4];
#pragma unroll
                for (int mi = 0; mi < 2; ++mi) {
                    uint32_t ad = st + (wm * 32 + mi * 16 + aRow) * PITCH
                                + (ks * 2 + aChk) * 16;
                    LDSM_X4(ah[mi][0], ah[mi][1], ah[mi][2], ah[mi][3], ad + T_A_HI);
                    LDSM_X4(al[mi][0], al[mi][1], al[mi][2], al[mi][3], ad + T_A_LO);
                }
#pragma unroll
                for (int g = 0; g < 4; ++g) {
                    uint32_t bh[4], bl[4];
                    uint32_t bd = st + (wn * 64 + g * 16 + bRow) * PITCH
                                + (ks * 2 + bChk) * 16;
                    LDSM_X4(bh[0], bh[1], bh[2], bh[3], bd + T_B_HI);
                    LDSM_X4(bl[0], bl[1], bl[2], bl[3], bd + T_B_LO);
#pragma unroll
                    for (int mi = 0; mi < 2; ++mi) {
                        MMA16816(acc[mi][2 * g],     ah[mi], bh[0], bh[1]);
                        MMA16816(acc[mi][2 * g + 1], ah[mi], bh[2], bh[3]);
                        MMA16816(acc[mi][2 * g],     ah[mi], bl[0], bl[1]);
                        MMA16816(acc[mi][2 * g + 1], ah[mi], bl[2], bl[3]);
                        MMA16816(acc[mi][2 * g],     al[mi], bh[0], bh[1]);
                        MMA16816(acc[mi][2 * g + 1], al[mi], bh[2], bh[3]);
                    }
                }
            }
            BAR(1, 256);
        }
#undef LOAD_STAGE

        BAR(0, 384);      // join: fp32 partials + norms ready

        // epilogue: dot = accT + pbuf; dist = fl(fl(zn+cn) + fl(-2*dot))
#pragma unroll
        for (int mi = 0; mi < 2; ++mi) {
            int rL = wm * 32 + mi * 16 + (lane >> 2);
            float znL = s_zn[rL], znH = s_zn[rL + 8];
#pragma unroll
            for (int n8 = 0; n8 < 8; ++n8) {
                int cloc = wn * 64 + n8 * 8 + (lane & 3) * 2;
                float cn0 = s_cn[cloc], cn1 = s_cn[cloc + 1];
                float* a = acc[mi][n8];
                float d0 = a[0] + pbuf[rL * 130 + cloc];
                float d1 = a[1] + pbuf[rL * 130 + cloc + 1];
                float d2 = a[2] + pbuf[(rL + 8) * 130 + cloc];
                float d3 = a[3] + pbuf[(rL + 8) * 130 + cloc + 1];
                float2 dl, dh;
                dl.x = __fadd_rn(__fadd_rn(znL, cn0), __fmul_rn(-2.f, d0));
                dl.y = __fadd_rn(__fadd_rn(znL, cn1), __fmul_rn(-2.f, d1));
                dh.x = __fadd_rn(__fadd_rn(znH, cn0), __fmul_rn(-2.f, d2));
                dh.y = __fadd_rn(__fadd_rn(znH, cn1), __fmul_rn(-2.f, d3));
                *(float2*)&g_dist[(size_t)(row0 + rL)     * 1024 + n0 + cloc] = dl;
                *(float2*)&g_dist[(size_t)(row0 + rL + 8) * 1024 + n0 + cloc] = dh;
            }
        }
    } else {
        // ================= FP32 GROUP (warps 8..11) =================
        const int ft = tid - 256;          // 0..127
        const int rr = ft & 31;
        const int cw = ft >> 5;            // warp id 0..3 -> 16-col group

        // norms into smem (consumed after BAR 0)
        s_cn[ft] = g_cnorm[n0 + ft];
        s_zn[ft] = g_znorm[row0 + ft];

        const float* zf = z + (size_t)bi * (DCH * HW) + rem0;
        const float* cf = cb + (size_t)(n0 + ft) * DCH;

#define F_LOAD(buf, ck) do {                                                   \
    int k0 = KF0 + (ck) * 8;                                                   \
    uint32_t zd = sb + F_Z + (buf) * 4096 + ft * 4;                            \
    _Pragma("unroll")                                                          \
    for (int k = 0; k < 8; ++k)                                                \
        cpasync4(zd + k * 512, zf + (size_t)(k0 + k) * HW + ft);               \
    uint32_t cd = sb + F_C + (buf) * 4096 + ft * 32;                           \
    cpasync16(cd,      cf + k0);                                               \
    cpasync16(cd + 16, cf + k0 + 4);                                           \
    CP_COMMIT();                                                               \
} while (0)

        for (int pass = 0; pass < 2; ++pass) {
            const int cbase = cw * 16 + pass * 64;
            float acc[4][16];
#pragma unroll
            for (int q = 0; q < 4; ++q)
#pragma unroll
                for (int c = 0; c < 16; ++c) acc[q][c] = 0.f;

            F_LOAD(0, 0);
#pragma unroll 1
            for (int ck = 0; ck < 16; ++ck) {
                if (ck + 1 < 16) F_LOAD((ck + 1) & 1, ck + 1);
                if (ck + 1 < 16) { CP_WAIT1(); } else { CP_WAIT0(); }
                BAR(2, 128);
                const float* zsb = (const float*)(smem + F_Z + (ck & 1) * 4096);
                const float* csb = (const float*)(smem + F_C + (ck & 1) * 4096);
#pragma unroll
                for (int k = 0; k < 8; ++k) {
                    float zv0 = zsb[k * 128 + rr];
                    float zv1 = zsb[k * 128 + rr + 32];
                    float zv2 = zsb[k * 128 + rr + 64];
                    float zv3 = zsb[k * 128 + rr + 96];
#pragma unroll
                    for (int c = 0; c < 16; ++c) {
                        float cv = csb[(cbase + c) * 8 + k];
                        acc[0][c] = fmaf(zv0, cv, acc[0][c]);
                        acc[1][c] = fmaf(zv1, cv, acc[1][c]);
                        acc[2][c] = fmaf(zv2, cv, acc[2][c]);
                        acc[3][c] = fmaf(zv3, cv, acc[3][c]);
                    }
                }
                BAR(2, 128);
            }
            // store partials
#pragma unroll
            for (int q = 0; q < 4; ++q)
#pragma unroll
                for (int c = 0; c < 16; ++c)
                    pbuf[(rr + 32 * q) * 130 + cbase + c] = acc[q][c];
        }
#undef F_LOAD
        BAR(0, 384);
    }
}

// ---------------------------------------------------------------------------
// k_prob: per-row argmin (first-index tie-break) + softmax + prob write
// ---------------------------------------------------------------------------
__global__ __launch_bounds__(256)
void k_prob(float* __restrict__ prob) {
    __shared__ float sval[4][64];
    __shared__ int   sidx[4][64];
    const int tid = threadIdx.x;
    const int rg  = tid >> 6;
    const int cl  = tid & 63;
    const int row = (blockIdx.x << 2) + rg;
    const size_t base = (size_t)row * 1024 + cl;

    float d[16];
    float mv = 3.4e38f; int mi = 0x7fffffff;
#pragma unroll
    for (int i = 0; i < 16; ++i) {
        d[i] = g_dist[base + 64 * i];
        int j = cl + 64 * i;
        if (d[i] < mv) { mv = d[i]; mi = j; }
    }
    sval[rg][cl] = mv; sidx[rg][cl] = mi;
    __syncthreads();
    for (int off = 32; off > 0; off >>= 1) {
        if (cl < off) {
            float v2 = sval[rg][cl + off]; int i2 = sidx[rg][cl + off];
            if (v2 < sval[rg][cl] || (v2 == sval[rg][cl] && i2 < sidx[rg][cl])) {
                sval[rg][cl] = v2; sidx[rg][cl] = i2;
            }
        }
        __syncthreads();
    }
    float m = sval[rg][0];
    if (cl == 0) g_minidx[row] = sidx[rg][0];
    __syncthreads();

    float e[16], s = 0.f;
#pragma unroll
    for (int i = 0; i < 16; ++i) {
        e[i] = __expf(__fmul_rn(-2.f, __fsub_rn(d[i], m)));
        s += e[i];
    }
    sval[rg][cl] = s;
    __syncthreads();
    for (int off = 32; off > 0; off >>= 1) {
        if (cl < off) sval[rg][cl] += sval[rg][cl + off];
        __syncthreads();
    }
    float invS = 1.0f / sval[rg][0];
    float* op = prob + base;
#pragma unroll
    for (int i = 0; i < 16; ++i)
        op[64 * i] = e[i] * invS;
}

// ---------------------------------------------------------------------------
// gather z_q + loss partials: 8192 blocks x (32 rows, 128-d chunk)
// ---------------------------------------------------------------------------
__global__ __launch_bounds__(256)
void k_gather(const float* __restrict__ z,
              const float* __restrict__ cb,
              float* __restrict__ outzq) {
    __shared__ float cbuf[128 * 33];
    __shared__ int   s_idx[32];
    __shared__ float sred[256];
    const int tid   = threadIdx.x;
    const int row0  = (blockIdx.x >> 2) << 5;
    const int dbase = (blockIdx.x & 3) << 7;
    const int bi    = row0 >> 12;
    const int rem0  = row0 & 4095;
    if (tid < 32) s_idx[tid] = g_minidx[row0 + tid];
    __syncthreads();

    // load 32 code rows x 128 d, store transposed [d][row]
#pragma unroll
    for (int i = tid; i < 4096; i += 256) {
        int r = i >> 7, c = i & 127;
        cbuf[c * 33 + r] = cb[(size_t)s_idx[r] * DCH + dbase + c];
    }
    __syncthreads();

    float lsum = 0.f;
    const size_t zb = (size_t)bi * (DCH * HW) + rem0;
#pragma unroll
    for (int it = 0; it < 16; ++it) {
        int l    = tid + (it << 8);
        int rloc = l & 31;
        int dloc = l >> 5;
        size_t gi = zb + (size_t)(dbase + dloc) * HW + rloc;
        float c  = cbuf[dloc * 33 + rloc];
        float zv = z[gi];
        float df = c - zv;
        lsum += df * df;
        outzq[gi] = c;
    }
    sred[tid] = lsum;
    __syncthreads();
    for (int off = 128; off > 0; off >>= 1) {
        if (tid < off) sred[tid] += sred[tid + off];
        __syncthreads();
    }
    if (tid == 0) g_partial[blockIdx.x] = sred[0];
}

__global__ void k_loss(float* __restrict__ out) {
    __shared__ float s[1024];
    int tid = threadIdx.x;
    float a = 0.f;
#pragma unroll
    for (int i = 0; i < 8; ++i) a += g_partial[tid + 1024 * i];
    s[tid] = a;
    __syncthreads();
    for (int off = 512; off > 0; off >>= 1) {
        if (tid < off) s[tid] += s[tid + off];
        __syncthreads();
    }
    if (tid == 0) out[0] = s[0] * (1.25f / 33554432.f);
}

// ---------------------------------------------------------------------------
extern "C" void kernel_launch(void* const* d_in, const int* in_sizes, int n_in,
                              void* d_out, int out_size) {
    const float* z  = (const float*)d_in[0];
    const float* cb = (const float*)d_in[1];
    float* out = (float*)d_out;

    cudaFuncSetAttribute(k_gemm, cudaFuncAttributeMaxDynamicSharedMemorySize, GEMM_SMEM);

    k_csplit<<<1024, 256>>>(cb);
    k_cnorm<<<4, 256>>>(cb);
    k_zsplit<<<1024, 256>>>(z);
    k_gemm<<<4096, 384, GEMM_SMEM>>>(z, cb);
    k_prob<<<16384, 256>>>(out + PROB_OFF);
    k_gather<<<8192, 256>>>(z, cb, out);
    k_loss<<<1, 1024>>>(out + LOSS_OFF);
}

// round 6
// speedup vs baseline: 1.4372x; 1.4372x over previous
#include <cuda_runtime.h>
#include <cuda_bf16.h>
#include <cstdint>

#define DCH   512
#define HW    4096
#define NROWS 65536
#define KCB   1024
#define LOSS_OFF 33554432
#define PROB_OFF 33554433

// ---------------- device scratch ----------------
__device__ float g_cnorm[KCB];
__device__ float g_znorm[NROWS];
__device__ int   g_minidx[NROWS];
__device__ float g_partial[8192];
__device__ __nv_bfloat16 g_zhi[(size_t)NROWS * DCH];
__device__ __nv_bfloat16 g_zlo[(size_t)NROWS * DCH];
__device__ __nv_bfloat16 g_chi[(size_t)KCB * DCH];
__device__ __nv_bfloat16 g_clo[(size_t)KCB * DCH];
__device__ float g_dist[(size_t)NROWS * KCB];

// ---------------- PTX helpers (sm_80-era, plain-target legal) ----------------
__device__ __forceinline__ uint32_t smem_u32(const void* p) {
    uint32_t a;
    asm("{ .reg .u64 t; cvta.to.shared.u64 t, %1; cvt.u32.u64 %0, t; }" : "=r"(a) : "l"(p));
    return a;
}
__device__ __forceinline__ void cpasync16(uint32_t s, const void* g) {
    asm volatile("cp.async.cg.shared.global [%0], [%1], 16;" :: "r"(s), "l"(g));
}
#define CP_COMMIT()  asm volatile("cp.async.commit_group;" ::: "memory")
#define CP_WAIT1()   asm volatile("cp.async.wait_group 1;" ::: "memory")
#define CP_WAIT0()   asm volatile("cp.async.wait_group 0;" ::: "memory")

#define LDSM_X4(r0, r1, r2, r3, addr)                                          \
    asm volatile("ldmatrix.sync.aligned.m8n8.x4.shared.b16 {%0,%1,%2,%3}, [%4];" \
                 : "=r"(r0), "=r"(r1), "=r"(r2), "=r"(r3) : "r"(addr))

#define MMA16816(d, a0, a1, a2, a3, b0, b1)                                    \
    asm volatile("mma.sync.aligned.m16n8k16.row.col.f32.bf16.bf16.f32 "        \
                 "{%0,%1,%2,%3}, {%4,%5,%6,%7}, {%8,%9}, {%0,%1,%2,%3};"       \
                 : "+f"((d)[0]), "+f"((d)[1]), "+f"((d)[2]), "+f"((d)[3])      \
                 : "r"(a0), "r"(a1), "r"(a2), "r"(a3), "r"(b0), "r"(b1))

// ---------------------------------------------------------------------------
// cnorm: sequential fp32 (replicates reference rounding)
// ---------------------------------------------------------------------------
__global__ void k_cnorm(const float* __restrict__ cb) {
    int j = blockIdx.x * blockDim.x + threadIdx.x;
    if (j >= KCB) return;
    const float* r = cb + (size_t)j * DCH;
    float acc = 0.f;
    for (int k = 0; k < DCH; ++k) {
        float v = r[k];
        acc = __fadd_rn(acc, __fmul_rn(v, v));
    }
    g_cnorm[j] = acc;
}

// ---------------------------------------------------------------------------
// codebook bf16 hi/lo split
// ---------------------------------------------------------------------------
__global__ void k_csplit(const float* __restrict__ cb) {
    int idx = blockIdx.x * blockDim.x + threadIdx.x;
    if (idx >= (KCB * DCH) / 2) return;
    float2 v = ((const float2*)cb)[idx];
    __nv_bfloat162 h = __floats2bfloat162_rn(v.x, v.y);
    float2 hf = make_float2(__bfloat162float(__low2bfloat16(h)),
                            __bfloat162float(__high2bfloat16(h)));
    __nv_bfloat162 l = __floats2bfloat162_rn(v.x - hf.x, v.y - hf.y);
    ((__nv_bfloat162*)g_chi)[idx] = h;
    ((__nv_bfloat162*)g_clo)[idx] = l;
}

// ---------------------------------------------------------------------------
// z bf16 hi/lo split + FUSED znorm (exact sequential d-order per row)
// ---------------------------------------------------------------------------
__global__ __launch_bounds__(256)
void k_zsplit(const float* __restrict__ z) {
    __shared__ float sm[64 * 65];
    const int tid  = threadIdx.x;
    const int bi   = blockIdx.x >> 6;
    const int rem0 = (blockIdx.x & 63) << 6;
    const float* zb = z + (size_t)bi * (DCH * HW) + rem0;
    float zacc = 0.f;

    for (int kt = 0; kt < 8; ++kt) {
        __syncthreads();
        int k0 = kt * 64;
#pragma unroll
        for (int it = 0; it < 16; ++it) {
            int li = it * 256 + tid;
            int r = li & 63, k = li >> 6;
            sm[k * 65 + r] = zb[(size_t)(k0 + k) * HW + r];
        }
        __syncthreads();
        if (tid < 64) {
#pragma unroll 8
            for (int k = 0; k < 64; ++k) {
                float v = sm[k * 65 + tid];
                zacc = __fadd_rn(zacc, __fmul_rn(v, v));
            }
        }
        int r  = tid >> 2;
        int kq = tid & 3;
        uint32_t hbuf[8], lbuf[8];
#pragma unroll
        for (int i = 0; i < 8; ++i) {
            float v0 = sm[(kq * 16 + 2 * i)     * 65 + r];
            float v1 = sm[(kq * 16 + 2 * i + 1) * 65 + r];
            __nv_bfloat162 h = __floats2bfloat162_rn(v0, v1);
            float h0 = __bfloat162float(__low2bfloat16(h));
            float h1 = __bfloat162float(__high2bfloat16(h));
            __nv_bfloat162 l = __floats2bfloat162_rn(v0 - h0, v1 - h1);
            hbuf[i] = *(uint32_t*)&h;
            lbuf[i] = *(uint32_t*)&l;
        }
        size_t base = ((size_t)(bi * 4096 + rem0 + r)) * DCH + k0 + kq * 16;
        *(uint4*)((char*)g_zhi + base * 2)      = *(uint4*)(hbuf);
        *(uint4*)((char*)g_zhi + base * 2 + 16) = *(uint4*)(hbuf + 4);
        *(uint4*)((char*)g_zlo + base * 2)      = *(uint4*)(lbuf);
        *(uint4*)((char*)g_zlo + base * 2 + 16) = *(uint4*)(lbuf + 4);
    }
    if (tid < 64) g_znorm[bi * 4096 + rem0 + tid] = zacc;
}

// ---------------------------------------------------------------------------
// HMMA GEMM + dist. CTA 128x128, K-chunk 32, 3-term bf16 split.
// Term-major MMA ordering (reuse distance 8) + 2 CTAs/SM.
// ---------------------------------------------------------------------------
#define PITCH 80
#define T_A_HI 0
#define T_A_LO 10240
#define T_B_HI 20480
#define T_B_LO 30720
#define STAGE_BYTES 40960
#define S_CN  81920
#define S_ZN  82432
#define GEMM_SMEM 82944

__global__ __launch_bounds__(256, 2)
void k_gemm() {
    extern __shared__ char smem[];
    const uint32_t sb = smem_u32(smem);
    const int tid   = threadIdx.x;
    const int lane  = tid & 31;
    const int wid   = tid >> 5;
    const int wm    = wid & 3;
    const int wn    = wid >> 2;
    const int rowblk = blockIdx.x >> 3;
    const int nblk   = blockIdx.x & 7;
    const int row0   = rowblk << 7;
    const int n0     = nblk << 7;

    const int srow = tid >> 2;
    const int sch  = tid & 3;

    const char* gAh = (const char*)g_zhi + ((size_t)(row0 + srow) << 10) + sch * 16;
    const char* gAl = (const char*)g_zlo + ((size_t)(row0 + srow) << 10) + sch * 16;
    const char* gBh = (const char*)g_chi + ((size_t)(n0   + srow) << 10) + sch * 16;
    const char* gBl = (const char*)g_clo + ((size_t)(n0   + srow) << 10) + sch * 16;
    const uint32_t sOff = srow * PITCH + sch * 16;

#define LOAD_STAGE(stg, kc) do {                                               \
    uint32_t s0 = sb + (stg) * STAGE_BYTES + sOff;                             \
    size_t   go = (size_t)(kc) * 64;                                           \
    cpasync16(s0 + T_A_HI,              gAh + go);                             \
    cpasync16(s0 + T_A_HI + 64 * PITCH, gAh + go + (size_t)64 * 1024);         \
    cpasync16(s0 + T_A_LO,              gAl + go);                             \
    cpasync16(s0 + T_A_LO + 64 * PITCH, gAl + go + (size_t)64 * 1024);         \
    cpasync16(s0 + T_B_HI,              gBh + go);                             \
    cpasync16(s0 + T_B_HI + 64 * PITCH, gBh + go + (size_t)64 * 1024);         \
    cpasync16(s0 + T_B_LO,              gBl + go);                             \
    cpasync16(s0 + T_B_LO + 64 * PITCH, gBl + go + (size_t)64 * 1024);         \
    CP_COMMIT();                                                               \
} while (0)

    LOAD_STAGE(0, 0);

    float* s_cn = (float*)(smem + S_CN);
    float* s_zn = (float*)(smem + S_ZN);
    if (tid < 128) {
        s_cn[tid] = g_cnorm[n0 + tid];
        s_zn[tid] = g_znorm[row0 + tid];
    }

    float acc[2][8][4];
#pragma unroll
    for (int mi = 0; mi < 2; ++mi)
#pragma unroll
        for (int n8 = 0; n8 < 8; ++n8)
#pragma unroll
            for (int e = 0; e < 4; ++e) acc[mi][n8][e] = 0.f;

    const int aRow = (lane & 15);
    const int aChk = (lane >> 4);
    const int bRow = (lane & 7) + ((lane >> 4) << 3);
    const int bChk = ((lane >> 3) & 1);

    for (int kc = 0; kc < 16; ++kc) {
        if (kc + 1 < 16) LOAD_STAGE((kc + 1) & 1, kc + 1);
        if (kc + 1 < 16) { CP_WAIT1(); } else { CP_WAIT0(); }
        __syncthreads();

        const uint32_t st = sb + (kc & 1) * STAGE_BYTES;
#pragma unroll
        for (int ks = 0; ks < 2; ++ks) {
            uint32_t ah[2][4], al[2][4];
#pragma unroll
            for (int mi = 0; mi < 2; ++mi) {
                uint32_t ad = st + (wm * 32 + mi * 16 + aRow) * PITCH
                            + (ks * 2 + aChk) * 16;
                LDSM_X4(ah[mi][0], ah[mi][1], ah[mi][2], ah[mi][3], ad + T_A_HI);
                LDSM_X4(al[mi][0], al[mi][1], al[mi][2], al[mi][3], ad + T_A_LO);
            }
#pragma unroll
            for (int gp = 0; gp < 2; ++gp) {
                const int g0 = 2 * gp, g1 = 2 * gp + 1;
                uint32_t b0h[4], b0l[4], b1h[4], b1l[4];
                uint32_t bd0 = st + (wn * 64 + g0 * 16 + bRow) * PITCH
                             + (ks * 2 + bChk) * 16;
                uint32_t bd1 = st + (wn * 64 + g1 * 16 + bRow) * PITCH
                             + (ks * 2 + bChk) * 16;
                LDSM_X4(b0h[0], b0h[1], b0h[2], b0h[3], bd0 + T_B_HI);
                LDSM_X4(b0l[0], b0l[1], b0l[2], b0l[3], bd0 + T_B_LO);
                LDSM_X4(b1h[0], b1h[1], b1h[2], b1h[3], bd1 + T_B_HI);
                LDSM_X4(b1l[0], b1l[1], b1l[2], b1l[3], bd1 + T_B_LO);

                // term hh (8 MMAs, 8 distinct accumulators)
                MMA16816(acc[0][2*g0],   ah[0][0],ah[0][1],ah[0][2],ah[0][3], b0h[0], b0h[1]);
                MMA16816(acc[0][2*g0+1], ah[0][0],ah[0][1],ah[0][2],ah[0][3], b0h[2], b0h[3]);
                MMA16816(acc[1][2*g0],   ah[1][0],ah[1][1],ah[1][2],ah[1][3], b0h[0], b0h[1]);
                MMA16816(acc[1][2*g0+1], ah[1][0],ah[1][1],ah[1][2],ah[1][3], b0h[2], b0h[3]);
                MMA16816(acc[0][2*g1],   ah[0][0],ah[0][1],ah[0][2],ah[0][3], b1h[0], b1h[1]);
                MMA16816(acc[0][2*g1+1], ah[0][0],ah[0][1],ah[0][2],ah[0][3], b1h[2], b1h[3]);
                MMA16816(acc[1][2*g1],   ah[1][0],ah[1][1],ah[1][2],ah[1][3], b1h[0], b1h[1]);
                MMA16816(acc[1][2*g1+1], ah[1][0],ah[1][1],ah[1][2],ah[1][3], b1h[2], b1h[3]);
                // term hl
                MMA16816(acc[0][2*g0],   ah[0][0],ah[0][1],ah[0][2],ah[0][3], b0l[0], b0l[1]);
                MMA16816(acc[0][2*g0+1], ah[0][0],ah[0][1],ah[0][2],ah[0][3], b0l[2], b0l[3]);
                MMA16816(acc[1][2*g0],   ah[1][0],ah[1][1],ah[1][2],ah[1][3], b0l[0], b0l[1]);
                MMA16816(acc[1][2*g0+1], ah[1][0],ah[1][1],ah[1][2],ah[1][3], b0l[2], b0l[3]);
                MMA16816(acc[0][2*g1],   ah[0][0],ah[0][1],ah[0][2],ah[0][3], b1l[0], b1l[1]);
                MMA16816(acc[0][2*g1+1], ah[0][0],ah[0][1],ah[0][2],ah[0][3], b1l[2], b1l[3]);
                MMA16816(acc[1][2*g1],   ah[1][0],ah[1][1],ah[1][2],ah[1][3], b1l[0], b1l[1]);
                MMA16816(acc[1][2*g1+1], ah[1][0],ah[1][1],ah[1][2],ah[1][3], b1l[2], b1l[3]);
                // term lh
                MMA16816(acc[0][2*g0],   al[0][0],al[0][1],al[0][2],al[0][3], b0h[0], b0h[1]);
                MMA16816(acc[0][2*g0+1], al[0][0],al[0][1],al[0][2],al[0][3], b0h[2], b0h[3]);
                MMA16816(acc[1][2*g0],   al[1][0],al[1][1],al[1][2],al[1][3], b0h[0], b0h[1]);
                MMA16816(acc[1][2*g0+1], al[1][0],al[1][1],al[1][2],al[1][3], b0h[2], b0h[3]);
                MMA16816(acc[0][2*g1],   al[0][0],al[0][1],al[0][2],al[0][3], b1h[0], b1h[1]);
                MMA16816(acc[0][2*g1+1], al[0][0],al[0][1],al[0][2],al[0][3], b1h[2], b1h[3]);
                MMA16816(acc[1][2*g1],   al[1][0],al[1][1],al[1][2],al[1][3], b1h[0], b1h[1]);
                MMA16816(acc[1][2*g1+1], al[1][0],al[1][1],al[1][2],al[1][3], b1h[2], b1h[3]);
            }
        }
        __syncthreads();
    }
#undef LOAD_STAGE

    // epilogue: dist = fl(fl(zn+cn) - 2*dot), float2 stores
#pragma unroll
    for (int mi = 0; mi < 2; ++mi) {
        int rL = wm * 32 + mi * 16 + (lane >> 2);
        float znL = s_zn[rL], znH = s_zn[rL + 8];
#pragma unroll
        for (int n8 = 0; n8 < 8; ++n8) {
            int cloc = wn * 64 + n8 * 8 + (lane & 3) * 2;
            float cn0 = s_cn[cloc], cn1 = s_cn[cloc + 1];
            float* a = acc[mi][n8];
            float2 dl, dh;
            dl.x = __fadd_rn(__fadd_rn(znL, cn0), __fmul_rn(-2.f, a[0]));
            dl.y = __fadd_rn(__fadd_rn(znL, cn1), __fmul_rn(-2.f, a[1]));
            dh.x = __fadd_rn(__fadd_rn(znH, cn0), __fmul_rn(-2.f, a[2]));
            dh.y = __fadd_rn(__fadd_rn(znH, cn1), __fmul_rn(-2.f, a[3]));
            *(float2*)&g_dist[(size_t)(row0 + rL)     * 1024 + n0 + cloc] = dl;
            *(float2*)&g_dist[(size_t)(row0 + rL + 8) * 1024 + n0 + cloc] = dh;
        }
    }
}

// ---------------------------------------------------------------------------
// k_prob: per-row argmin (first-index tie-break) + softmax + prob write
// ---------------------------------------------------------------------------
__global__ __launch_bounds__(256)
void k_prob(float* __restrict__ prob) {
    __shared__ float sval[4][64];
    __shared__ int   sidx[4][64];
    const int tid = threadIdx.x;
    const int rg  = tid >> 6;
    const int cl  = tid & 63;
    const int row = (blockIdx.x << 2) + rg;
    const size_t base = (size_t)row * 1024 + cl;

    float d[16];
    float mv = 3.4e38f; int mi = 0x7fffffff;
#pragma unroll
    for (int i = 0; i < 16; ++i) {
        d[i] = g_dist[base + 64 * i];
        int j = cl + 64 * i;
        if (d[i] < mv) { mv = d[i]; mi = j; }
    }
    sval[rg][cl] = mv; sidx[rg][cl] = mi;
    __syncthreads();
    for (int off = 32; off > 0; off >>= 1) {
        if (cl < off) {
            float v2 = sval[rg][cl + off]; int i2 = sidx[rg][cl + off];
            if (v2 < sval[rg][cl] || (v2 == sval[rg][cl] && i2 < sidx[rg][cl])) {
                sval[rg][cl] = v2; sidx[rg][cl] = i2;
            }
        }
        __syncthreads();
    }
    float m = sval[rg][0];
    if (cl == 0) g_minidx[row] = sidx[rg][0];
    __syncthreads();

    float e[16], s = 0.f;
#pragma unroll
    for (int i = 0; i < 16; ++i) {
        e[i] = __expf(__fmul_rn(-2.f, __fsub_rn(d[i], m)));
        s += e[i];
    }
    sval[rg][cl] = s;
    __syncthreads();
    for (int off = 32; off > 0; off >>= 1) {
        if (cl < off) sval[rg][cl] += sval[rg][cl + off];
        __syncthreads();
    }
    float invS = 1.0f / sval[rg][0];
    float* op = prob + base;
#pragma unroll
    for (int i = 0; i < 16; ++i)
        op[64 * i] = e[i] * invS;
}

// ---------------------------------------------------------------------------
// gather z_q + loss partials: 8192 blocks x (32 rows, 128-d chunk)
// ---------------------------------------------------------------------------
__global__ __launch_bounds__(256)
void k_gather(const float* __restrict__ z,
              const float* __restrict__ cb,
              float* __restrict__ outzq) {
    __shared__ float cbuf[128 * 33];
    __shared__ int   s_idx[32];
    __shared__ float sred[256];
    const int tid   = threadIdx.x;
    const int row0  = (blockIdx.x >> 2) << 5;
    const int dbase = (blockIdx.x & 3) << 7;
    const int bi    = row0 >> 12;
    const int rem0  = row0 & 4095;
    if (tid < 32) s_idx[tid] = g_minidx[row0 + tid];
    __syncthreads();

#pragma unroll
    for (int i = tid; i < 4096; i += 256) {
        int r = i >> 7, c = i & 127;
        cbuf[c * 33 + r] = cb[(size_t)s_idx[r] * DCH + dbase + c];
    }
    __syncthreads();

    float lsum = 0.f;
    const size_t zb = (size_t)bi * (DCH * HW) + rem0;
#pragma unroll
    for (int it = 0; it < 16; ++it) {
        int l    = tid + (it << 8);
        int rloc = l & 31;
        int dloc = l >> 5;
        size_t gi = zb + (size_t)(dbase + dloc) * HW + rloc;
        float c  = cbuf[dloc * 33 + rloc];
        float zv = z[gi];
        float df = c - zv;
        lsum += df * df;
        outzq[gi] = c;
    }
    sred[tid] = lsum;
    __syncthreads();
    for (int off = 128; off > 0; off >>= 1) {
        if (tid < off) sred[tid] += sred[tid + off];
        __syncthreads();
    }
    if (tid == 0) g_partial[blockIdx.x] = sred[0];
}

__global__ void k_loss(float* __restrict__ out) {
    __shared__ float s[1024];
    int tid = threadIdx.x;
    float a = 0.f;
#pragma unroll
    for (int i = 0; i < 8; ++i) a += g_partial[tid + 1024 * i];
    s[tid] = a;
    __syncthreads();
    for (int off = 512; off > 0; off >>= 1) {
        if (tid < off) s[tid] += s[tid + off];
        __syncthreads();
    }
    if (tid == 0) out[0] = s[0] * (1.25f / 33554432.f);
}

// ---------------------------------------------------------------------------
extern "C" void kernel_launch(void* const* d_in, const int* in_sizes, int n_in,
                              void* d_out, int out_size) {
    const float* z  = (const float*)d_in[0];
    const float* cb = (const float*)d_in[1];
    float* out = (float*)d_out;

    cudaFuncSetAttribute(k_gemm, cudaFuncAttributeMaxDynamicSharedMemorySize, GEMM_SMEM);

    k_csplit<<<1024, 256>>>(cb);
    k_cnorm<<<4, 256>>>(cb);
    k_zsplit<<<1024, 256>>>(z);
    k_gemm<<<4096, 256, GEMM_SMEM>>>();
    k_prob<<<16384, 256>>>(out + PROB_OFF);
    k_gather<<<8192, 256>>>(z, cb, out);
    k_loss<<<1, 1024>>>(out + LOSS_OFF);
}

// round 7
// speedup vs baseline: 1.4974x; 1.0419x over previous
#include <cuda_runtime.h>
#include <cuda_bf16.h>
#include <cstdint>

#define DCH   512
#define HW    4096
#define NROWS 65536
#define KCB   1024
#define LOSS_OFF 33554432
#define PROB_OFF 33554433

// ---------------- device scratch ----------------
__device__ float g_cnorm[KCB];
__device__ float g_znorm[NROWS];
__device__ int   g_minidx[NROWS];
__device__ float g_partial[8192];
__device__ __nv_bfloat16 g_zhi[(size_t)NROWS * DCH];
__device__ __nv_bfloat16 g_zlo[(size_t)NROWS * DCH];
__device__ __nv_bfloat16 g_chi[(size_t)KCB * DCH];
__device__ __nv_bfloat16 g_clo[(size_t)KCB * DCH];
__device__ float g_dist[(size_t)NROWS * KCB];

// ---------------- PTX helpers (sm_80-era, plain-target legal) ----------------
__device__ __forceinline__ uint32_t smem_u32(const void* p) {
    uint32_t a;
    asm("{ .reg .u64 t; cvta.to.shared.u64 t, %1; cvt.u32.u64 %0, t; }" : "=r"(a) : "l"(p));
    return a;
}
__device__ __forceinline__ void cpasync16(uint32_t s, const void* g) {
    asm volatile("cp.async.cg.shared.global [%0], [%1], 16;" :: "r"(s), "l"(g));
}
#define CP_COMMIT()  asm volatile("cp.async.commit_group;" ::: "memory")
#define CP_WAIT0()   asm volatile("cp.async.wait_group 0;" ::: "memory")

#define LDSM_X4(r0, r1, r2, r3, addr)                                          \
    asm volatile("ldmatrix.sync.aligned.m8n8.x4.shared.b16 {%0,%1,%2,%3}, [%4];" \
                 : "=r"(r0), "=r"(r1), "=r"(r2), "=r"(r3) : "r"(addr))

// NOTE: non-volatile — pure register op, lets ptxas software-pipeline
#define MMA16816(d, a0, a1, a2, a3, b0, b1)                                    \
    asm("mma.sync.aligned.m16n8k16.row.col.f32.bf16.bf16.f32 "                 \
        "{%0,%1,%2,%3}, {%4,%5,%6,%7}, {%8,%9}, {%0,%1,%2,%3};"                \
        : "+f"((d)[0]), "+f"((d)[1]), "+f"((d)[2]), "+f"((d)[3])               \
        : "r"(a0), "r"(a1), "r"(a2), "r"(a3), "r"(b0), "r"(b1))

// ---------------------------------------------------------------------------
// codebook bf16 hi/lo split + fused cnorm (sequential fp32, reference order)
// ---------------------------------------------------------------------------
__global__ void k_csplit(const float* __restrict__ cb) {
    int idx = blockIdx.x * blockDim.x + threadIdx.x;
    if (idx < (KCB * DCH) / 2) {
        float2 v = ((const float2*)cb)[idx];
        __nv_bfloat162 h = __floats2bfloat162_rn(v.x, v.y);
        float2 hf = make_float2(__bfloat162float(__low2bfloat16(h)),
                                __bfloat162float(__high2bfloat16(h)));
        __nv_bfloat162 l = __floats2bfloat162_rn(v.x - hf.x, v.y - hf.y);
        ((__nv_bfloat162*)g_chi)[idx] = h;
        ((__nv_bfloat162*)g_clo)[idx] = l;
    }
    // one thread per code row computes cnorm (first 1024 threads globally)
    int j = blockIdx.x * blockDim.x + threadIdx.x;
    if (blockIdx.x < 4) {
        int jj = blockIdx.x * 256 + threadIdx.x;
        const float* r = cb + (size_t)jj * DCH;
        float acc = 0.f;
        for (int k = 0; k < DCH; ++k) {
            float v = r[k];
            acc = __fadd_rn(acc, __fmul_rn(v, v));
        }
        g_cnorm[jj] = acc;
    }
    (void)j;
}

// ---------------------------------------------------------------------------
// z bf16 hi/lo split + FUSED znorm (exact sequential d-order per row)
// ---------------------------------------------------------------------------
__global__ __launch_bounds__(256)
void k_zsplit(const float* __restrict__ z) {
    __shared__ float sm[64 * 65];
    const int tid  = threadIdx.x;
    const int bi   = blockIdx.x >> 6;
    const int rem0 = (blockIdx.x & 63) << 6;
    const float* zb = z + (size_t)bi * (DCH * HW) + rem0;
    float zacc = 0.f;

    for (int kt = 0; kt < 8; ++kt) {
        __syncthreads();
        int k0 = kt * 64;
#pragma unroll
        for (int it = 0; it < 16; ++it) {
            int li = it * 256 + tid;
            int r = li & 63, k = li >> 6;
            sm[k * 65 + r] = zb[(size_t)(k0 + k) * HW + r];
        }
        __syncthreads();
        if (tid < 64) {
#pragma unroll 8
            for (int k = 0; k < 64; ++k) {
                float v = sm[k * 65 + tid];
                zacc = __fadd_rn(zacc, __fmul_rn(v, v));
            }
        }
        int r  = tid >> 2;
        int kq = tid & 3;
        uint32_t hbuf[8], lbuf[8];
#pragma unroll
        for (int i = 0; i < 8; ++i) {
            float v0 = sm[(kq * 16 + 2 * i)     * 65 + r];
            float v1 = sm[(kq * 16 + 2 * i + 1) * 65 + r];
            __nv_bfloat162 h = __floats2bfloat162_rn(v0, v1);
            float h0 = __bfloat162float(__low2bfloat16(h));
            float h1 = __bfloat162float(__high2bfloat16(h));
            __nv_bfloat162 l = __floats2bfloat162_rn(v0 - h0, v1 - h1);
            hbuf[i] = *(uint32_t*)&h;
            lbuf[i] = *(uint32_t*)&l;
        }
        size_t base = ((size_t)(bi * 4096 + rem0 + r)) * DCH + k0 + kq * 16;
        *(uint4*)((char*)g_zhi + base * 2)      = *(uint4*)(hbuf);
        *(uint4*)((char*)g_zhi + base * 2 + 16) = *(uint4*)(hbuf + 4);
        *(uint4*)((char*)g_zlo + base * 2)      = *(uint4*)(lbuf);
        *(uint4*)((char*)g_zlo + base * 2 + 16) = *(uint4*)(lbuf + 4);
    }
    if (tid < 64) g_znorm[bi * 4096 + rem0 + tid] = zacc;
}

// ---------------------------------------------------------------------------
// HMMA GEMM + dist. CTA 128x128, K-chunk 32, 3-term bf16 split.
// Term-major MMA ordering, 2 CTAs/SM, ONE barrier per k-chunk.
// ---------------------------------------------------------------------------
#define PITCH 80
#define T_A_HI 0
#define T_A_LO 10240
#define T_B_HI 20480
#define T_B_LO 30720
#define STAGE_BYTES 40960
#define S_CN  81920
#define S_ZN  82432
#define GEMM_SMEM 82944

__global__ __launch_bounds__(256, 2)
void k_gemm() {
    extern __shared__ char smem[];
    const uint32_t sb = smem_u32(smem);
    const int tid   = threadIdx.x;
    const int lane  = tid & 31;
    const int wid   = tid >> 5;
    const int wm    = wid & 3;
    const int wn    = wid >> 2;
    const int rowblk = blockIdx.x >> 3;
    const int nblk   = blockIdx.x & 7;
    const int row0   = rowblk << 7;
    const int n0     = nblk << 7;

    const int srow = tid >> 2;
    const int sch  = tid & 3;

    const char* gAh = (const char*)g_zhi + ((size_t)(row0 + srow) << 10) + sch * 16;
    const char* gAl = (const char*)g_zlo + ((size_t)(row0 + srow) << 10) + sch * 16;
    const char* gBh = (const char*)g_chi + ((size_t)(n0   + srow) << 10) + sch * 16;
    const char* gBl = (const char*)g_clo + ((size_t)(n0   + srow) << 10) + sch * 16;
    const uint32_t sOff = srow * PITCH + sch * 16;

#define LOAD_STAGE(stg, kc) do {                                               \
    uint32_t s0 = sb + (stg) * STAGE_BYTES + sOff;                             \
    size_t   go = (size_t)(kc) * 64;                                           \
    cpasync16(s0 + T_A_HI,              gAh + go);                             \
    cpasync16(s0 + T_A_HI + 64 * PITCH, gAh + go + (size_t)64 * 1024);         \
    cpasync16(s0 + T_A_LO,              gAl + go);                             \
    cpasync16(s0 + T_A_LO + 64 * PITCH, gAl + go + (size_t)64 * 1024);         \
    cpasync16(s0 + T_B_HI,              gBh + go);                             \
    cpasync16(s0 + T_B_HI + 64 * PITCH, gBh + go + (size_t)64 * 1024);         \
    cpasync16(s0 + T_B_LO,              gBl + go);                             \
    cpasync16(s0 + T_B_LO + 64 * PITCH, gBl + go + (size_t)64 * 1024);         \
    CP_COMMIT();                                                               \
} while (0)

    LOAD_STAGE(0, 0);

    float* s_cn = (float*)(smem + S_CN);
    float* s_zn = (float*)(smem + S_ZN);
    if (tid < 128) {
        s_cn[tid] = g_cnorm[n0 + tid];
        s_zn[tid] = g_znorm[row0 + tid];
    }

    float acc[2][8][4];
#pragma unroll
    for (int mi = 0; mi < 2; ++mi)
#pragma unroll
        for (int n8 = 0; n8 < 8; ++n8)
#pragma unroll
            for (int e = 0; e < 4; ++e) acc[mi][n8][e] = 0.f;

    const int aRow = (lane & 15);
    const int aChk = (lane >> 4);
    const int bRow = (lane & 7) + ((lane >> 4) << 3);
    const int bChk = ((lane >> 3) & 1);

    for (int kc = 0; kc < 16; ++kc) {
        // one barrier per k-chunk: stage(kc) arrived AND all warps finished
        // computing on the buffer that load(kc+1) will overwrite.
        CP_WAIT0();
        __syncthreads();
        if (kc + 1 < 16) LOAD_STAGE((kc + 1) & 1, kc + 1);

        const uint32_t st = sb + (kc & 1) * STAGE_BYTES;
#pragma unroll
        for (int ks = 0; ks < 2; ++ks) {
            uint32_t ah[2][4], al[2][4];
#pragma unroll
            for (int mi = 0; mi < 2; ++mi) {
                uint32_t ad = st + (wm * 32 + mi * 16 + aRow) * PITCH
                            + (ks * 2 + aChk) * 16;
                LDSM_X4(ah[mi][0], ah[mi][1], ah[mi][2], ah[mi][3], ad + T_A_HI);
                LDSM_X4(al[mi][0], al[mi][1], al[mi][2], al[mi][3], ad + T_A_LO);
            }
#pragma unroll
            for (int gp = 0; gp < 2; ++gp) {
                const int g0 = 2 * gp, g1 = 2 * gp + 1;
                uint32_t b0h[4], b0l[4], b1h[4], b1l[4];
                uint32_t bd0 = st + (wn * 64 + g0 * 16 + bRow) * PITCH
                             + (ks * 2 + bChk) * 16;
                uint32_t bd1 = st + (wn * 64 + g1 * 16 + bRow) * PITCH
                             + (ks * 2 + bChk) * 16;
                LDSM_X4(b0h[0], b0h[1], b0h[2], b0h[3], bd0 + T_B_HI);
                LDSM_X4(b0l[0], b0l[1], b0l[2], b0l[3], bd0 + T_B_LO);
                LDSM_X4(b1h[0], b1h[1], b1h[2], b1h[3], bd1 + T_B_HI);
                LDSM_X4(b1l[0], b1l[1], b1l[2], b1l[3], bd1 + T_B_LO);

                // term hh (8 distinct accumulators)
                MMA16816(acc[0][2*g0],   ah[0][0],ah[0][1],ah[0][2],ah[0][3], b0h[0], b0h[1]);
                MMA16816(acc[0][2*g0+1], ah[0][0],ah[0][1],ah[0][2],ah[0][3], b0h[2], b0h[3]);
                MMA16816(acc[1][2*g0],   ah[1][0],ah[1][1],ah[1][2],ah[1][3], b0h[0], b0h[1]);
                MMA16816(acc[1][2*g0+1], ah[1][0],ah[1][1],ah[1][2],ah[1][3], b0h[2], b0h[3]);
                MMA16816(acc[0][2*g1],   ah[0][0],ah[0][1],ah[0][2],ah[0][3], b1h[0], b1h[1]);
                MMA16816(acc[0][2*g1+1], ah[0][0],ah[0][1],ah[0][2],ah[0][3], b1h[2], b1h[3]);
                MMA16816(acc[1][2*g1],   ah[1][0],ah[1][1],ah[1][2],ah[1][3], b1h[0], b1h[1]);
                MMA16816(acc[1][2*g1+1], ah[1][0],ah[1][1],ah[1][2],ah[1][3], b1h[2], b1h[3]);
                // term hl
                MMA16816(acc[0][2*g0],   ah[0][0],ah[0][1],ah[0][2],ah[0][3], b0l[0], b0l[1]);
                MMA16816(acc[0][2*g0+1], ah[0][0],ah[0][1],ah[0][2],ah[0][3], b0l[2], b0l[3]);
                MMA16816(acc[1][2*g0],   ah[1][0],ah[1][1],ah[1][2],ah[1][3], b0l[0], b0l[1]);
                MMA16816(acc[1][2*g0+1], ah[1][0],ah[1][1],ah[1][2],ah[1][3], b0l[2], b0l[3]);
                MMA16816(acc[0][2*g1],   ah[0][0],ah[0][1],ah[0][2],ah[0][3], b1l[0], b1l[1]);
                MMA16816(acc[0][2*g1+1], ah[0][0],ah[0][1],ah[0][2],ah[0][3], b1l[2], b1l[3]);
                MMA16816(acc[1][2*g1],   ah[1][0],ah[1][1],ah[1][2],ah[1][3], b1l[0], b1l[1]);
                MMA16816(acc[1][2*g1+1], ah[1][0],ah[1][1],ah[1][2],ah[1][3], b1l[2], b1l[3]);
                // term lh
                MMA16816(acc[0][2*g0],   al[0][0],al[0][1],al[0][2],al[0][3], b0h[0], b0h[1]);
                MMA16816(acc[0][2*g0+1], al[0][0],al[0][1],al[0][2],al[0][3], b0h[2], b0h[3]);
                MMA16816(acc[1][2*g0],   al[1][0],al[1][1],al[1][2],al[1][3], b0h[0], b0h[1]);
                MMA16816(acc[1][2*g0+1], al[1][0],al[1][1],al[1][2],al[1][3], b0h[2], b0h[3]);
                MMA16816(acc[0][2*g1],   al[0][0],al[0][1],al[0][2],al[0][3], b1h[0], b1h[1]);
                MMA16816(acc[0][2*g1+1], al[0][0],al[0][1],al[0][2],al[0][3], b1h[2], b1h[3]);
                MMA16816(acc[1][2*g1],   al[1][0],al[1][1],al[1][2],al[1][3], b1h[0], b1h[1]);
                MMA16816(acc[1][2*g1+1], al[1][0],al[1][1],al[1][2],al[1][3], b1h[2], b1h[3]);
            }
        }
    }
#undef LOAD_STAGE

    // epilogue: dist = fl(fl(zn+cn) - 2*dot), float2 stores
#pragma unroll
    for (int mi = 0; mi < 2; ++mi) {
        int rL = wm * 32 + mi * 16 + (lane >> 2);
        float znL = s_zn[rL], znH = s_zn[rL + 8];
#pragma unroll
        for (int n8 = 0; n8 < 8; ++n8) {
            int cloc = wn * 64 + n8 * 8 + (lane & 3) * 2;
            float cn0 = s_cn[cloc], cn1 = s_cn[cloc + 1];
            float* a = acc[mi][n8];
            float2 dl, dh;
            dl.x = __fadd_rn(__fadd_rn(znL, cn0), __fmul_rn(-2.f, a[0]));
            dl.y = __fadd_rn(__fadd_rn(znL, cn1), __fmul_rn(-2.f, a[1]));
            dh.x = __fadd_rn(__fadd_rn(znH, cn0), __fmul_rn(-2.f, a[2]));
            dh.y = __fadd_rn(__fadd_rn(znH, cn1), __fmul_rn(-2.f, a[3]));
            *(float2*)&g_dist[(size_t)(row0 + rL)     * 1024 + n0 + cloc] = dl;
            *(float2*)&g_dist[(size_t)(row0 + rL + 8) * 1024 + n0 + cloc] = dh;
        }
    }
}

// ---------------------------------------------------------------------------
// k_prob: per-row argmin (first-index tie-break) + softmax + prob write
// ---------------------------------------------------------------------------
__global__ __launch_bounds__(256)
void k_prob(float* __restrict__ prob) {
    __shared__ float sval[4][64];
    __shared__ int   sidx[4][64];
    const int tid = threadIdx.x;
    const int rg  = tid >> 6;
    const int cl  = tid & 63;
    const int row = (blockIdx.x << 2) + rg;
    const size_t base = (size_t)row * 1024 + cl;

    float d[16];
    float mv = 3.4e38f; int mi = 0x7fffffff;
#pragma unroll
    for (int i = 0; i < 16; ++i) {
        d[i] = g_dist[base + 64 * i];
        int j = cl + 64 * i;
        if (d[i] < mv) { mv = d[i]; mi = j; }
    }
    sval[rg][cl] = mv; sidx[rg][cl] = mi;
    __syncthreads();
    for (int off = 32; off > 0; off >>= 1) {
        if (cl < off) {
            float v2 = sval[rg][cl + off]; int i2 = sidx[rg][cl + off];
            if (v2 < sval[rg][cl] || (v2 == sval[rg][cl] && i2 < sidx[rg][cl])) {
                sval[rg][cl] = v2; sidx[rg][cl] = i2;
            }
        }
        __syncthreads();
    }
    float m = sval[rg][0];
    if (cl == 0) g_minidx[row] = sidx[rg][0];
    __syncthreads();

    float e[16], s = 0.f;
#pragma unroll
    for (int i = 0; i < 16; ++i) {
        e[i] = __expf(__fmul_rn(-2.f, __fsub_rn(d[i], m)));
        s += e[i];
    }
    sval[rg][cl] = s;
    __syncthreads();
    for (int off = 32; off > 0; off >>= 1) {
        if (cl < off) sval[rg][cl] += sval[rg][cl + off];
        __syncthreads();
    }
    float invS = 1.0f / sval[rg][0];
    float* op = prob + base;
#pragma unroll
    for (int i = 0; i < 16; ++i)
        op[64 * i] = e[i] * invS;
}

// ---------------------------------------------------------------------------
// gather z_q + loss partials: 8192 blocks x (32 rows, 128-d chunk)
// ---------------------------------------------------------------------------
__global__ __launch_bounds__(256)
void k_gather(const float* __restrict__ z,
              const float* __restrict__ cb,
              float* __restrict__ outzq) {
    __shared__ float cbuf[128 * 33];
    __shared__ int   s_idx[32];
    __shared__ float sred[256];
    const int tid   = threadIdx.x;
    const int row0  = (blockIdx.x >> 2) << 5;
    const int dbase = (blockIdx.x & 3) << 7;
    const int bi    = row0 >> 12;
    const int rem0  = row0 & 4095;
    if (tid < 32) s_idx[tid] = g_minidx[row0 + tid];
    __syncthreads();

#pragma unroll
    for (int i = tid; i < 4096; i += 256) {
        int r = i >> 7, c = i & 127;
        cbuf[c * 33 + r] = cb[(size_t)s_idx[r] * DCH + dbase + c];
    }
    __syncthreads();

    float lsum = 0.f;
    const size_t zb = (size_t)bi * (DCH * HW) + rem0;
#pragma unroll
    for (int it = 0; it < 16; ++it) {
        int l    = tid + (it << 8);
        int rloc = l & 31;
        int dloc = l >> 5;
        size_t gi = zb + (size_t)(dbase + dloc) * HW + rloc;
        float c  = cbuf[dloc * 33 + rloc];
        float zv = z[gi];
        float df = c - zv;
        lsum += df * df;
        outzq[gi] = c;
    }
    sred[tid] = lsum;
    __syncthreads();
    for (int off = 128; off > 0; off >>= 1) {
        if (tid < off) sred[tid] += sred[tid + off];
        __syncthreads();
    }
    if (tid == 0) g_partial[blockIdx.x] = sred[0];
}

__global__ void k_loss(float* __restrict__ out) {
    __shared__ float s[1024];
    int tid = threadIdx.x;
    float a = 0.f;
#pragma unroll
    for (int i = 0; i < 8; ++i) a += g_partial[tid + 1024 * i];
    s[tid] = a;
    __syncthreads();
    for (int off = 512; off > 0; off >>= 1) {
        if (tid < off) s[tid] += s[tid + off];
        __syncthreads();
    }
    if (tid == 0) out[0] = s[0] * (1.25f / 33554432.f);
}

// ---------------------------------------------------------------------------
extern "C" void kernel_launch(void* const* d_in, const int* in_sizes, int n_in,
                              void* d_out, int out_size) {
    const float* z  = (const float*)d_in[0];
    const float* cb = (const float*)d_in[1];
    float* out = (float*)d_out;

    cudaFuncSetAttribute(k_gemm, cudaFuncAttributeMaxDynamicSharedMemorySize, GEMM_SMEM);

    k_csplit<<<1024, 256>>>(cb);
    k_zsplit<<<1024, 256>>>(z);
    k_gemm<<<4096, 256, GEMM_SMEM>>>();
    k_prob<<<16384, 256>>>(out + PROB_OFF);
    k_gather<<<8192, 256>>>(z, cb, out);
    k_loss<<<1, 1024>>>(out + LOSS_OFF);
}